// round 12
// baseline (speedup 1.0000x reference)
#include <cuda_runtime.h>
#include <cuda_fp16.h>

// ---------------------------------------------------------------------------
// NetMHCpan BiLSTM:  pep BiLSTM (T=15) + HLA BiLSTM (T=372), H=1024,
// then MLP 4096 -> 4096 (relu) -> 1.
//
// Persistent cooperative kernel, 128 CTAs, unit-per-warp (R11 structure):
// warp w owns hidden unit 8*cta+w of its direction (f = warps 0-7,
// b = warps 8-15); groups sync only via named barriers (bar.sync 1/2, 256).
//
// R12: straggler-tail attack.
//  * h broadcast is SPLIT IN HALVES with two per-(dir,step) counters:
//    producer CTAs 0-63 feed cols 0-511, CTAs 64-127 feed cols 512-1023.
//    Consumers poll lo -> fetch -> GEMV half1 (hides hi-half stragglers)
//    -> poll hi -> fetch -> GEMV half2.
//  * tight ld.acquire.gpu spin (no nanosleep) -- kills wakeup quantization.
//  * producer publish unchanged from R11 (proven): st.cg h -> threadfence ->
//    smem atomicAdd; 8th warp does ONE red.global.gpu.add to its half-counter.
// ---------------------------------------------------------------------------

#define H      1024
#define G4     4096
#define LPEP   15
#define LHLA   372
#define NCTA   128
#define NHU    8      // hidden units per CTA per direction
#define NROWS  32     // gate rows per CTA per direction
#define NTHR   512    // 16 warps: 0-7 dir f, 8-15 dir b
#define NWARP  16
#define TMAX   400
#define HALF_THRESH 64u
#define SPIN_LIMIT (1u << 22)

// SMEM: weights 2*32*1024 half (131072 B) + h_f/h_b double-parity (16384 B)
#define SMEM_BYTES (2 * NROWS * H * 2 + 2 * 2 * H * 4)

struct Ptrs {
    const float* wih[4];
    const float* whh[4];
    const float* bih[4];
    const float* bhh[4];
};

// -------------------- device scratch (no allocations allowed) ---------------
__device__ float    g_xg[4 * LHLA * G4];    // input projections (24.4 MB)
__device__ float    g_h[4 * 2 * H];         // per-direction double-buffered h
__device__ unsigned g_cnt[4 * 2 * TMAX];    // per-(dir,half,step) counters
__device__ float    g_h1[G4];               // MLP hidden activations

__device__ __forceinline__ float tanh_fast(float x) {
    float y;
    asm("tanh.approx.f32 %0, %1;" : "=f"(y) : "f"(x));
    return y;
}
__device__ __forceinline__ float sigmoid_fast(float x) {
    return fmaf(tanh_fast(0.5f * x), 0.5f, 0.5f);
}
__device__ __forceinline__ void red_add_gpu(unsigned* p, unsigned v) {
    asm volatile("red.global.gpu.add.u32 [%0], %1;" :: "l"(p), "r"(v) : "memory");
}
__device__ __forceinline__ unsigned ld_acquire(const unsigned* p) {
    unsigned v;
    asm volatile("ld.global.acquire.gpu.u32 %0, [%1];" : "=r"(v) : "l"(p));
    return v;
}
#define GROUP_BAR(id) asm volatile("bar.sync %0, 256;" :: "r"(id) : "memory")

// ---------------------------------------------------------------------------
// Prep: blocks 0-63 compute xg[d][t][row] = x_t @ wih.T + bih + bhh;
// block 64: counters (HALF_THRESH at t=0, else 0); block 65: zero g_h.
// d: 0=pep_f 1=pep_b 2=hla_f 3=hla_b (backward dirs consume reversed input).
// ---------------------------------------------------------------------------
__global__ void prep_kernel(const float* __restrict__ in_pep,
                            const float* __restrict__ in_hla,
                            Ptrs p)
{
    __shared__ float sx[LHLA * 21];    // 31.2 KB
    const int bid = blockIdx.x;
    const int tid = threadIdx.x;

    if (bid >= 64) {
        if (bid == 64) {
            for (int i = tid; i < 4 * 2 * TMAX; i += 256)
                g_cnt[i] = ((i % TMAX) == 0) ? HALF_THRESH : 0u;
        } else {
            for (int i = tid; i < 4 * 2 * H; i += 256) g_h[i] = 0.0f;
        }
        return;
    }

    const int d  = bid >> 4;
    const int rb = bid & 15;
    const int T  = (d < 2) ? LPEP : LHLA;
    const float* src = (d < 2) ? in_pep : in_hla;
    const bool rev = (d & 1);

    for (int i = tid; i < T * 21; i += 256) {
        int t = i / 21, j = i - t * 21;
        int ts = rev ? (T - 1 - t) : t;
        sx[t * 21 + j] = src[ts * 21 + j];
    }
    __syncthreads();

    const int row = rb * 256 + tid;
    float w[21];
    const float* wp = p.wih[d] + (size_t)row * 21;
#pragma unroll
    for (int j = 0; j < 21; ++j) w[j] = wp[j];
    const float b = p.bih[d][row] + p.bhh[d][row];

    float* out = g_xg + (size_t)d * LHLA * G4 + row;
    for (int t = 0; t < T; ++t) {
        float acc = b;
#pragma unroll
        for (int j = 0; j < 21; ++j) acc = fmaf(w[j], sx[t * 21 + j], acc);
        out[(size_t)t * G4] = acc;
    }
}

// ---------------------------------------------------------------------------
// Persistent BiLSTM kernel: 512 threads, dir-f = warps 0-7, dir-b = 8-15.
// ---------------------------------------------------------------------------
__global__ void __launch_bounds__(NTHR, 1) lstm_kernel(Ptrs p)
{
    extern __shared__ unsigned char smem[];
    __half2* wt    = (__half2*)smem;                       // [2][32][512] half2
    float*   h_smf = (float*)(smem + 2 * NROWS * H * 2);   // [2][1024]
    float*   h_smb = h_smf + 2 * H;                        // [2][1024]
    __shared__ unsigned s_cnt[2];                          // per-group arrivals

    const int tid  = threadIdx.x;
    const int lane = tid & 31;
    const int warp = tid >> 5;
    const int cta  = blockIdx.x;
    const int grpb = (warp >= 8);       // 0 = dir f, 1 = dir b
    const int w    = warp & 7;          // unit within CTA slice
    const int qloc = tid & 255;         // thread index within group

    for (int phase = 0; phase < 2; ++phase) {
        const int d = 2 * phase + grpb;
        const int T = phase ? LHLA : LPEP;

        // ---- all threads: load 2 dirs x 32 gate rows of whh as fp16 ----
        for (int rr = warp; rr < 2 * NROWS; rr += NWARP) {
            const int x = rr >> 5;          // 0=f, 1=b
            const int r = rr & 31;          // g*8 + u
            const int g = r >> 3, u = r & 7;
            const float4* src = (const float4*)
                (p.whh[2 * phase + x] + ((size_t)(g * H + 8 * cta + u)) * H);
            __half2* dst = wt + (size_t)rr * 512;
            for (int k = lane; k < 256; k += 32) {
                float4 f = src[k];
                dst[2 * k]     = __floats2half2_rn(f.x, f.y);
                dst[2 * k + 1] = __floats2half2_rn(f.z, f.w);
            }
        }
        if (tid < 2) s_cnt[tid] = 0u;
        __syncthreads();                    // weights + counters ready

        float*    hb    = g_h + d * 2 * H;
        unsigned* cn_lo = g_cnt + d * 2 * TMAX;         // CTAs 0-63
        unsigned* cn_hi = cn_lo + TMAX;                 // CTAs 64-127
        unsigned* cn_my = (cta < 64) ? cn_lo : cn_hi;   // publish target
        const float* xg = g_xg + (size_t)d * LHLA * G4;
        const __half2* wtd = wt + (grpb ? NROWS * 512 : 0);
        float* h_sm = grpb ? h_smb : h_smf;
        const int barid = 1 + grpb;
        float c_u = 0.0f;                   // cell state (lane 0 of each warp)

        for (int t = 0; t < T; ++t) {
            // lane0: prefetch this unit's 4 xg gate values
            float x0 = 0.f, x1 = 0.f, x2 = 0.f, x3 = 0.f;
            if (lane == 0) {
                const float* xp = xg + (size_t)t * G4 + 8 * cta + w;
                x0 = __ldg(xp);
                x1 = __ldg(xp + H);
                x2 = __ldg(xp + 2 * H);
                x3 = __ldg(xp + 3 * H);
            }

            const int par = t & 1;
            float* hsv = h_sm + par * H;
            float a0 = 0.f, a1 = 0.f, a2 = 0.f, a3 = 0.f;

            // ============ two halves, pipelined against stragglers ========
#pragma unroll
            for (int hh = 0; hh < 2; ++hh) {
                // one poller per group: tight acquire-spin on half counter
                if (w == 0 && lane == 0) {
                    unsigned* c = hh ? &cn_hi[t] : &cn_lo[t];
                    unsigned spins = 0;
                    while (ld_acquire(c) < HALF_THRESH && ++spins < SPIN_LIMIT)
                        ;
                }
                GROUP_BAR(barid);           // half hh globally ready

                // burst fetch 512 floats: 256 threads x float2
                {
                    const float2* hs = (const float2*)(hb + par * H + hh * 512);
                    ((float2*)(hsv + hh * 512))[qloc] = __ldcg(hs + qloc);
                }
                GROUP_BAR(barid);           // half hh in SMEM

                // GEMV on cols [hh*512, hh*512+512)
                float hr[16];
#pragma unroll
                for (int g = 0; g < 2; ++g) {
                    const int gg = hh * 2 + g;
                    ((float4*)hr)[2 * g]     = ((const float4*)hsv)[gg * 64 + lane * 2];
                    ((float4*)hr)[2 * g + 1] = ((const float4*)hsv)[gg * 64 + lane * 2 + 1];
                }
#pragma unroll
                for (int gate = 0; gate < 4; ++gate) {
                    float* ap = (gate == 0) ? &a0 : (gate == 1) ? &a1
                              : (gate == 2) ? &a2 : &a3;
                    const uint4* wrow =
                        (const uint4*)(wtd + (size_t)(gate * 8 + w) * 512);
                    float acc = *ap;
#pragma unroll
                    for (int g = 0; g < 2; ++g) {
                        const int c4 = hh * 2 + g;
                        uint4 wq = wrow[c4 * 32 + lane];
                        float2 f0 = __half22float2(*(const __half2*)&wq.x);
                        float2 f1 = __half22float2(*(const __half2*)&wq.y);
                        float2 f2 = __half22float2(*(const __half2*)&wq.z);
                        float2 f3 = __half22float2(*(const __half2*)&wq.w);
                        acc = fmaf(f0.x, hr[8 * g + 0], acc);
                        acc = fmaf(f0.y, hr[8 * g + 1], acc);
                        acc = fmaf(f1.x, hr[8 * g + 2], acc);
                        acc = fmaf(f1.y, hr[8 * g + 3], acc);
                        acc = fmaf(f2.x, hr[8 * g + 4], acc);
                        acc = fmaf(f2.y, hr[8 * g + 5], acc);
                        acc = fmaf(f3.x, hr[8 * g + 6], acc);
                        acc = fmaf(f3.y, hr[8 * g + 7], acc);
                    }
                    *ap = acc;
                }
            }

            // reduce 4 accumulators across the warp
#pragma unroll
            for (int s = 16; s >= 1; s >>= 1) {
                a0 += __shfl_xor_sync(0xffffffffu, a0, s);
                a1 += __shfl_xor_sync(0xffffffffu, a1, s);
                a2 += __shfl_xor_sync(0xffffffffu, a2, s);
                a3 += __shfl_xor_sync(0xffffffffu, a3, s);
            }

            // lane0: cell + immediate publish (R11-proven pattern)
            if (lane == 0) {
                float zi = a0 + x0, zf = a1 + x1, zg = a2 + x2, zo = a3 + x3;
                c_u = fmaf(sigmoid_fast(zf), c_u,
                           sigmoid_fast(zi) * tanh_fast(zg));
                float hn = sigmoid_fast(zo) * tanh_fast(c_u);
                __stcg(&hb[((t + 1) & 1) * H + 8 * cta + w], hn);
                __threadfence();            // release h before arrival
                unsigned old = atomicAdd(&s_cnt[grpb], 1u);
                if (old == (unsigned)(8 * t + 7))      // 8th warp of this step
                    red_add_gpu(&cn_my[t + 1], 1u);
            }
        }
        __syncthreads();                    // wt reads done before reload
    }
}

// ---------------------------------------------------------------------------
// MLP: h1 = relu(x @ w1.T + b1), y = h1 @ w2.T + b2.
// x = [pep_f, pep_b, hla_f, hla_b]; pep finals in buf 1 (T=15), hla in buf 0.
// ---------------------------------------------------------------------------
__global__ void mlp1_kernel(const float* __restrict__ w1, const float* __restrict__ b1)
{
    __shared__ float sx[G4];
    const int tid = threadIdx.x, lane = tid & 31, warp = tid >> 5;

    for (int k = tid; k < G4; k += 256) {
        int dd = k >> 10;
        int kk = k & 1023;
        int buf = (dd < 2) ? 1 : 0;    // pep T=15 -> buf 1, hla T=372 -> buf 0
        sx[k] = g_h[dd * 2 * H + buf * H + kk];
    }
    __syncthreads();

#pragma unroll
    for (int rep = 0; rep < 2; ++rep) {
        const int j = blockIdx.x * 16 + rep * 8 + warp;
        const float* wrow = w1 + (size_t)j * G4;
        float acc = 0.0f;
#pragma unroll 8
        for (int i = 0; i < 128; ++i)
            acc = fmaf(wrow[i * 32 + lane], sx[i * 32 + lane], acc);
        acc += __shfl_xor_sync(0xffffffffu, acc, 16);
        acc += __shfl_xor_sync(0xffffffffu, acc, 8);
        acc += __shfl_xor_sync(0xffffffffu, acc, 4);
        acc += __shfl_xor_sync(0xffffffffu, acc, 2);
        acc += __shfl_xor_sync(0xffffffffu, acc, 1);
        if (lane == 0) g_h1[j] = fmaxf(acc + b1[j], 0.0f);
    }
}

__global__ void mlp2_kernel(const float* __restrict__ w2, const float* __restrict__ b2,
                            float* __restrict__ out)
{
    __shared__ float red[32];
    const int tid = threadIdx.x, lane = tid & 31, warp = tid >> 5;
    float acc = 0.0f;
    for (int k = tid; k < G4; k += 1024)
        acc = fmaf(g_h1[k], w2[k], acc);
    acc += __shfl_xor_sync(0xffffffffu, acc, 16);
    acc += __shfl_xor_sync(0xffffffffu, acc, 8);
    acc += __shfl_xor_sync(0xffffffffu, acc, 4);
    acc += __shfl_xor_sync(0xffffffffu, acc, 2);
    acc += __shfl_xor_sync(0xffffffffu, acc, 1);
    if (lane == 0) red[warp] = acc;
    __syncthreads();
    if (warp == 0) {
        float v = red[lane];
        v += __shfl_xor_sync(0xffffffffu, v, 16);
        v += __shfl_xor_sync(0xffffffffu, v, 8);
        v += __shfl_xor_sync(0xffffffffu, v, 4);
        v += __shfl_xor_sync(0xffffffffu, v, 2);
        v += __shfl_xor_sync(0xffffffffu, v, 1);
        if (lane == 0) out[0] = v + b2[0];
    }
}

// ---------------------------------------------------------------------------
extern "C" void kernel_launch(void* const* d_in, const int* in_sizes, int n_in,
                              void* d_out, int out_size)
{
    (void)in_sizes; (void)n_in; (void)out_size;

    const float* in_pep = (const float*)d_in[0];
    const float* in_hla = (const float*)d_in[1];

    Ptrs p;
    // input order: [wih, whh, bih, bhh] for pep_f, pep_b, hla_f, hla_b
    for (int d = 0; d < 4; ++d) {
        p.wih[d] = (const float*)d_in[2 + 4 * d];
        p.whh[d] = (const float*)d_in[3 + 4 * d];
        p.bih[d] = (const float*)d_in[4 + 4 * d];
        p.bhh[d] = (const float*)d_in[5 + 4 * d];
    }
    const float* w1 = (const float*)d_in[18];
    const float* b1 = (const float*)d_in[19];
    const float* w2 = (const float*)d_in[20];
    const float* b2 = (const float*)d_in[21];

    cudaFuncSetAttribute(lstm_kernel, cudaFuncAttributeMaxDynamicSharedMemorySize,
                         SMEM_BYTES);

    prep_kernel<<<66, 256>>>(in_pep, in_hla, p);
    lstm_kernel<<<NCTA, NTHR, SMEM_BYTES>>>(p);
    mlp1_kernel<<<256, 256>>>(w1, b1);
    mlp2_kernel<<<1, 1024>>>(w2, b2, (float*)d_out);
}

// round 13
// speedup vs baseline: 1.2251x; 1.2251x over previous
#include <cuda_runtime.h>
#include <cuda_fp16.h>

// ---------------------------------------------------------------------------
// NetMHCpan BiLSTM:  pep BiLSTM (T=15) + HLA BiLSTM (T=372), H=1024,
// then MLP 4096 -> 4096 (relu) -> 1.
//
// Persistent cooperative kernel, 128 CTAs, unit-per-warp (R11 structure):
// warp w owns hidden unit 8*cta+w of its direction (f = warps 0-7,
// b = warps 8-15); groups sync only via named barriers (bar.sync 1/2, 256).
//
// R13: SMEM BANK-CONFLICT FIX on the h loads. h_sm uses a permuted layout:
//   slot[c4*64 + p*32 + lane] = h[c4*256 + lane*8 + p*4 .. +4]
// so each warp's hr float4 loads are 16B/lane contiguous (conflict-free,
// 4 cyc) instead of 32B-strided (8-way conflict, 32 cyc). This removes
// ~3000 cycles/step of crossbar serialization. FFMA order is bit-identical
// to R11 -> rel_err must stay exactly 1.0884e-4.
// ---------------------------------------------------------------------------

#define H      1024
#define G4     4096
#define LPEP   15
#define LHLA   372
#define NCTA   128
#define NHU    8      // hidden units per CTA per direction
#define NROWS  32     // gate rows per CTA per direction
#define NTHR   512    // 16 warps: 0-7 dir f, 8-15 dir b
#define NWARP  16
#define TMAX   400
#define SPIN_LIMIT (1u << 22)

// SMEM: weights 2*32*1024 half (131072 B) + h_f/h_b double-parity (16384 B)
#define SMEM_BYTES (2 * NROWS * H * 2 + 2 * 2 * H * 4)

struct Ptrs {
    const float* wih[4];
    const float* whh[4];
    const float* bih[4];
    const float* bhh[4];
};

// -------------------- device scratch (no allocations allowed) ---------------
__device__ float    g_xg[4 * LHLA * G4];    // input projections (24.4 MB)
__device__ float    g_h[4 * 2 * H];         // per-direction double-buffered h
__device__ unsigned g_cnt[4 * TMAX];        // per-(dir,step) arrival counters
__device__ float    g_h1[G4];               // MLP hidden activations

__device__ __forceinline__ float tanh_fast(float x) {
    float y;
    asm("tanh.approx.f32 %0, %1;" : "=f"(y) : "f"(x));
    return y;
}
__device__ __forceinline__ float sigmoid_fast(float x) {
    return fmaf(tanh_fast(0.5f * x), 0.5f, 0.5f);
}
__device__ __forceinline__ void red_add_gpu(unsigned* p, unsigned v) {
    asm volatile("red.global.gpu.add.u32 [%0], %1;" :: "l"(p), "r"(v) : "memory");
}
__device__ __forceinline__ unsigned ld_acquire(const unsigned* p) {
    unsigned v;
    asm volatile("ld.global.acquire.gpu.u32 %0, [%1];" : "=r"(v) : "l"(p));
    return v;
}
#define GROUP_BAR(id) asm volatile("bar.sync %0, 256;" :: "r"(id) : "memory")

// ---------------------------------------------------------------------------
// Prep: blocks 0-63 compute xg[d][t][row] = x_t @ wih.T + bih + bhh;
// block 64: counters (NCTA at t=0, else 0); block 65: zero g_h.
// d: 0=pep_f 1=pep_b 2=hla_f 3=hla_b (backward dirs consume reversed input).
// ---------------------------------------------------------------------------
__global__ void prep_kernel(const float* __restrict__ in_pep,
                            const float* __restrict__ in_hla,
                            Ptrs p)
{
    __shared__ float sx[LHLA * 21];    // 31.2 KB
    const int bid = blockIdx.x;
    const int tid = threadIdx.x;

    if (bid >= 64) {
        if (bid == 64) {
            for (int i = tid; i < 4 * TMAX; i += 256)
                g_cnt[i] = ((i % TMAX) == 0) ? (unsigned)NCTA : 0u;
        } else {
            for (int i = tid; i < 4 * 2 * H; i += 256) g_h[i] = 0.0f;
        }
        return;
    }

    const int d  = bid >> 4;
    const int rb = bid & 15;
    const int T  = (d < 2) ? LPEP : LHLA;
    const float* src = (d < 2) ? in_pep : in_hla;
    const bool rev = (d & 1);

    for (int i = tid; i < T * 21; i += 256) {
        int t = i / 21, j = i - t * 21;
        int ts = rev ? (T - 1 - t) : t;
        sx[t * 21 + j] = src[ts * 21 + j];
    }
    __syncthreads();

    const int row = rb * 256 + tid;
    float w[21];
    const float* wp = p.wih[d] + (size_t)row * 21;
#pragma unroll
    for (int j = 0; j < 21; ++j) w[j] = wp[j];
    const float b = p.bih[d][row] + p.bhh[d][row];

    float* out = g_xg + (size_t)d * LHLA * G4 + row;
    for (int t = 0; t < T; ++t) {
        float acc = b;
#pragma unroll
        for (int j = 0; j < 21; ++j) acc = fmaf(w[j], sx[t * 21 + j], acc);
        out[(size_t)t * G4] = acc;
    }
}

// ---------------------------------------------------------------------------
// Persistent BiLSTM kernel: 512 threads, dir-f = warps 0-7, dir-b = 8-15.
// ---------------------------------------------------------------------------
__global__ void __launch_bounds__(NTHR, 1) lstm_kernel(Ptrs p)
{
    extern __shared__ unsigned char smem[];
    __half2* wt    = (__half2*)smem;                       // [2][32][512] half2
    float*   h_smf = (float*)(smem + 2 * NROWS * H * 2);   // [2][1024] permuted
    float*   h_smb = h_smf + 2 * H;                        // [2][1024] permuted
    __shared__ unsigned s_cnt[2];                          // per-group arrivals

    const int tid  = threadIdx.x;
    const int lane = tid & 31;
    const int warp = tid >> 5;
    const int cta  = blockIdx.x;
    const int grpb = (warp >= 8);       // 0 = dir f, 1 = dir b
    const int w    = warp & 7;          // unit within CTA slice
    const int qloc = tid & 255;         // thread index within group

    // permuted-fetch source index: thread k stages slot k of h_sm, whose
    // global float4 index is j = (k>>6)*64 + (k&31)*2 + ((k>>5)&1)
    const int jfetch = (qloc >> 6) * 64 + (qloc & 31) * 2 + ((qloc >> 5) & 1);

    for (int phase = 0; phase < 2; ++phase) {
        const int d = 2 * phase + grpb;
        const int T = phase ? LHLA : LPEP;

        // ---- all threads: load 2 dirs x 32 gate rows of whh as fp16 ----
        for (int rr = warp; rr < 2 * NROWS; rr += NWARP) {
            const int x = rr >> 5;          // 0=f, 1=b
            const int r = rr & 31;          // g*8 + u
            const int g = r >> 3, u = r & 7;
            const float4* src = (const float4*)
                (p.whh[2 * phase + x] + ((size_t)(g * H + 8 * cta + u)) * H);
            __half2* dst = wt + (size_t)rr * 512;
            for (int k = lane; k < 256; k += 32) {
                float4 f = src[k];
                dst[2 * k]     = __floats2half2_rn(f.x, f.y);
                dst[2 * k + 1] = __floats2half2_rn(f.z, f.w);
            }
        }
        if (tid < 2) s_cnt[tid] = 0u;
        __syncthreads();                    // weights + counters ready

        float*    hb  = g_h + d * 2 * H;
        unsigned* cn  = g_cnt + d * TMAX;
        const float* xg = g_xg + (size_t)d * LHLA * G4;
        const __half2* wtd = wt + (grpb ? NROWS * 512 : 0);
        float* h_sm = grpb ? h_smb : h_smf;
        const int barid = 1 + grpb;
        float c_u = 0.0f;                   // cell state (lane 0 of each warp)

        for (int t = 0; t < T; ++t) {
            // lane0: prefetch this unit's 4 xg gate values
            float x0 = 0.f, x1 = 0.f, x2 = 0.f, x3 = 0.f;
            if (lane == 0) {
                const float* xp = xg + (size_t)t * G4 + 8 * cta + w;
                x0 = __ldg(xp);
                x1 = __ldg(xp + H);
                x2 = __ldg(xp + 2 * H);
                x3 = __ldg(xp + 3 * H);
            }

            // one poller per group: tight acquire-spin on the counter
            if (w == 0 && lane == 0) {
                unsigned spins = 0;
                while (ld_acquire(&cn[t]) < (unsigned)NCTA &&
                       ++spins < SPIN_LIMIT)
                    ;
            }
            GROUP_BAR(barid);               // h(t) globally ready

            const int par = t & 1;
            float* hsv = h_sm + par * H;

            // burst fetch h(t) into PERMUTED SMEM layout:
            // slot k = [c4*64 + p*32 + lane] <- global float4 jfetch
            {
                const float4* hs = (const float4*)(hb + par * H);
                ((float4*)hsv)[qloc] = __ldcg(hs + jfetch);
            }
            GROUP_BAR(barid);               // h(t) in SMEM

            // ---- unit GEMV: 4 gate rows of unit w ----
            // hr chunk c4 holds h[c4*256 + lane*8 .. +8]; loads are now
            // 16B/lane contiguous (conflict-free)
            float hr[32];
#pragma unroll
            for (int c4 = 0; c4 < 4; ++c4) {
                ((float4*)hr)[2 * c4]     = ((const float4*)hsv)[c4 * 64 + lane];
                ((float4*)hr)[2 * c4 + 1] = ((const float4*)hsv)[c4 * 64 + 32 + lane];
            }
            float a0 = 0.f, a1 = 0.f, a2 = 0.f, a3 = 0.f;
#pragma unroll
            for (int gate = 0; gate < 4; ++gate) {
                float* ap = (gate == 0) ? &a0 : (gate == 1) ? &a1
                          : (gate == 2) ? &a2 : &a3;
                const uint4* wrow =
                    (const uint4*)(wtd + (size_t)(gate * 8 + w) * 512);
                float acc = 0.0f;
#pragma unroll
                for (int c4 = 0; c4 < 4; ++c4) {
                    uint4 wq = wrow[c4 * 32 + lane];   // cols c4*256+lane*8..+7
                    float2 f0 = __half22float2(*(const __half2*)&wq.x);
                    float2 f1 = __half22float2(*(const __half2*)&wq.y);
                    float2 f2 = __half22float2(*(const __half2*)&wq.z);
                    float2 f3 = __half22float2(*(const __half2*)&wq.w);
                    acc = fmaf(f0.x, hr[8 * c4 + 0], acc);
                    acc = fmaf(f0.y, hr[8 * c4 + 1], acc);
                    acc = fmaf(f1.x, hr[8 * c4 + 2], acc);
                    acc = fmaf(f1.y, hr[8 * c4 + 3], acc);
                    acc = fmaf(f2.x, hr[8 * c4 + 4], acc);
                    acc = fmaf(f2.y, hr[8 * c4 + 5], acc);
                    acc = fmaf(f3.x, hr[8 * c4 + 6], acc);
                    acc = fmaf(f3.y, hr[8 * c4 + 7], acc);
                }
                *ap = acc;
            }
#pragma unroll
            for (int s = 16; s >= 1; s >>= 1) {
                a0 += __shfl_xor_sync(0xffffffffu, a0, s);
                a1 += __shfl_xor_sync(0xffffffffu, a1, s);
                a2 += __shfl_xor_sync(0xffffffffu, a2, s);
                a3 += __shfl_xor_sync(0xffffffffu, a3, s);
            }

            // lane0: cell + immediate publish (R11-proven pattern)
            if (lane == 0) {
                float zi = a0 + x0, zf = a1 + x1, zg = a2 + x2, zo = a3 + x3;
                c_u = fmaf(sigmoid_fast(zf), c_u,
                           sigmoid_fast(zi) * tanh_fast(zg));
                float hn = sigmoid_fast(zo) * tanh_fast(c_u);
                __stcg(&hb[((t + 1) & 1) * H + 8 * cta + w], hn);
                __threadfence();            // release h before arrival
                unsigned old = atomicAdd(&s_cnt[grpb], 1u);
                if (old == (unsigned)(8 * t + 7))      // 8th warp of this step
                    red_add_gpu(&cn[t + 1], 1u);
            }
        }
        __syncthreads();                    // wt reads done before reload
    }
}

// ---------------------------------------------------------------------------
// MLP: h1 = relu(x @ w1.T + b1), y = h1 @ w2.T + b2.
// x = [pep_f, pep_b, hla_f, hla_b]; pep finals in buf 1 (T=15), hla in buf 0.
// ---------------------------------------------------------------------------
__global__ void mlp1_kernel(const float* __restrict__ w1, const float* __restrict__ b1)
{
    __shared__ float sx[G4];
    const int tid = threadIdx.x, lane = tid & 31, warp = tid >> 5;

    for (int k = tid; k < G4; k += 256) {
        int dd = k >> 10;
        int kk = k & 1023;
        int buf = (dd < 2) ? 1 : 0;    // pep T=15 -> buf 1, hla T=372 -> buf 0
        sx[k] = g_h[dd * 2 * H + buf * H + kk];
    }
    __syncthreads();

#pragma unroll
    for (int rep = 0; rep < 2; ++rep) {
        const int j = blockIdx.x * 16 + rep * 8 + warp;
        const float* wrow = w1 + (size_t)j * G4;
        float acc = 0.0f;
#pragma unroll 8
        for (int i = 0; i < 128; ++i)
            acc = fmaf(wrow[i * 32 + lane], sx[i * 32 + lane], acc);
        acc += __shfl_xor_sync(0xffffffffu, acc, 16);
        acc += __shfl_xor_sync(0xffffffffu, acc, 8);
        acc += __shfl_xor_sync(0xffffffffu, acc, 4);
        acc += __shfl_xor_sync(0xffffffffu, acc, 2);
        acc += __shfl_xor_sync(0xffffffffu, acc, 1);
        if (lane == 0) g_h1[j] = fmaxf(acc + b1[j], 0.0f);
    }
}

__global__ void mlp2_kernel(const float* __restrict__ w2, const float* __restrict__ b2,
                            float* __restrict__ out)
{
    __shared__ float red[32];
    const int tid = threadIdx.x, lane = tid & 31, warp = tid >> 5;
    float acc = 0.0f;
    for (int k = tid; k < G4; k += 1024)
        acc = fmaf(g_h1[k], w2[k], acc);
    acc += __shfl_xor_sync(0xffffffffu, acc, 16);
    acc += __shfl_xor_sync(0xffffffffu, acc, 8);
    acc += __shfl_xor_sync(0xffffffffu, acc, 4);
    acc += __shfl_xor_sync(0xffffffffu, acc, 2);
    acc += __shfl_xor_sync(0xffffffffu, acc, 1);
    if (lane == 0) red[warp] = acc;
    __syncthreads();
    if (warp == 0) {
        float v = red[lane];
        v += __shfl_xor_sync(0xffffffffu, v, 16);
        v += __shfl_xor_sync(0xffffffffu, v, 8);
        v += __shfl_xor_sync(0xffffffffu, v, 4);
        v += __shfl_xor_sync(0xffffffffu, v, 2);
        v += __shfl_xor_sync(0xffffffffu, v, 1);
        if (lane == 0) out[0] = v + b2[0];
    }
}

// ---------------------------------------------------------------------------
extern "C" void kernel_launch(void* const* d_in, const int* in_sizes, int n_in,
                              void* d_out, int out_size)
{
    (void)in_sizes; (void)n_in; (void)out_size;

    const float* in_pep = (const float*)d_in[0];
    const float* in_hla = (const float*)d_in[1];

    Ptrs p;
    // input order: [wih, whh, bih, bhh] for pep_f, pep_b, hla_f, hla_b
    for (int d = 0; d < 4; ++d) {
        p.wih[d] = (const float*)d_in[2 + 4 * d];
        p.whh[d] = (const float*)d_in[3 + 4 * d];
        p.bih[d] = (const float*)d_in[4 + 4 * d];
        p.bhh[d] = (const float*)d_in[5 + 4 * d];
    }
    const float* w1 = (const float*)d_in[18];
    const float* b1 = (const float*)d_in[19];
    const float* w2 = (const float*)d_in[20];
    const float* b2 = (const float*)d_in[21];

    cudaFuncSetAttribute(lstm_kernel, cudaFuncAttributeMaxDynamicSharedMemorySize,
                         SMEM_BYTES);

    prep_kernel<<<66, 256>>>(in_pep, in_hla, p);
    lstm_kernel<<<NCTA, NTHR, SMEM_BYTES>>>(p);
    mlp1_kernel<<<256, 256>>>(w1, b1);
    mlp2_kernel<<<1, 1024>>>(w2, b2, (float*)d_out);
}

// round 14
// speedup vs baseline: 1.6367x; 1.3360x over previous
#include <cuda_runtime.h>
#include <cuda_fp16.h>

// ---------------------------------------------------------------------------
// NetMHCpan BiLSTM:  pep BiLSTM (T=15) + HLA BiLSTM (T=372), H=1024,
// then MLP 4096 -> 4096 (relu) -> 1.
//
// Persistent cooperative kernel, 128 CTAs, dir-f = warps 0-7, dir-b = 8-15
// (groups sync only via named barriers). R14: TENSOR-CORE GEMV.
//
//  * whh lives in REGISTERS as m16n8k16 A-fragments (64 half2/warp, loaded
//    once per phase). Warp (m = w&1, ks = w>>1) computes rows [m*16,m*16+16)
//    over K slice [ks*256, ks*256+256): 16 HMMA/step vs ~280 FFMA+CVT instr.
//  * h broadcast is converted to half2 in SMEM; B-fragments are 2 broadcast
//    LDS.32 per mma (h replicated across the N dimension; col 0 extracted).
//  * Single-publisher epilogue: per-K-slice partials -> SMEM -> publisher
//    warp combines + cell + ONE threadfence per dir-group (2/step vs 16).
//  * Sync scaffold identical to R11/R13 (proven): per-(dir,step) counter,
//    acquire-spin poller, burst fetch, REDG publish.
// ---------------------------------------------------------------------------

#define H      1024
#define G4     4096
#define LPEP   15
#define LHLA   372
#define NCTA   128
#define NTHR   512    // 16 warps: 0-7 dir f, 8-15 dir b
#define TMAX   400
#define SPIN_LIMIT (1u << 22)

struct Ptrs {
    const float* wih[4];
    const float* whh[4];
    const float* bih[4];
    const float* bhh[4];
};

// -------------------- device scratch (no allocations allowed) ---------------
__device__ float    g_xg[4 * LHLA * G4];    // input projections (24.4 MB)
__device__ float    g_h[4 * 2 * H];         // per-direction double-buffered h
__device__ unsigned g_cnt[4 * TMAX];        // per-(dir,step) arrival counters
__device__ float    g_h1[G4];               // MLP hidden activations

__device__ __forceinline__ float tanh_fast(float x) {
    float y;
    asm("tanh.approx.f32 %0, %1;" : "=f"(y) : "f"(x));
    return y;
}
__device__ __forceinline__ float sigmoid_fast(float x) {
    return fmaf(tanh_fast(0.5f * x), 0.5f, 0.5f);
}
__device__ __forceinline__ void red_add_gpu(unsigned* p, unsigned v) {
    asm volatile("red.global.gpu.add.u32 [%0], %1;" :: "l"(p), "r"(v) : "memory");
}
__device__ __forceinline__ unsigned ld_acquire(const unsigned* p) {
    unsigned v;
    asm volatile("ld.global.acquire.gpu.u32 %0, [%1];" : "=r"(v) : "l"(p));
    return v;
}
__device__ __forceinline__ unsigned h2u(__half2 h) {
    return *reinterpret_cast<unsigned*>(&h);
}
__device__ __forceinline__ void mma16816(float& d0, float& d1, float& d2, float& d3,
                                         unsigned a0, unsigned a1, unsigned a2,
                                         unsigned a3, unsigned b0, unsigned b1)
{
    asm volatile(
        "mma.sync.aligned.m16n8k16.row.col.f32.f16.f16.f32 "
        "{%0,%1,%2,%3}, {%4,%5,%6,%7}, {%8,%9}, {%0,%1,%2,%3};"
        : "+f"(d0), "+f"(d1), "+f"(d2), "+f"(d3)
        : "r"(a0), "r"(a1), "r"(a2), "r"(a3), "r"(b0), "r"(b1));
}
#define GROUP_BAR(id) asm volatile("bar.sync %0, 256;" :: "r"(id) : "memory")

// ---------------------------------------------------------------------------
// Prep: blocks 0-63 compute xg[d][t][row] = x_t @ wih.T + bih + bhh;
// block 64: counters (NCTA at t=0, else 0); block 65: zero g_h.
// d: 0=pep_f 1=pep_b 2=hla_f 3=hla_b (backward dirs consume reversed input).
// ---------------------------------------------------------------------------
__global__ void prep_kernel(const float* __restrict__ in_pep,
                            const float* __restrict__ in_hla,
                            Ptrs p)
{
    __shared__ float sx[LHLA * 21];    // 31.2 KB
    const int bid = blockIdx.x;
    const int tid = threadIdx.x;

    if (bid >= 64) {
        if (bid == 64) {
            for (int i = tid; i < 4 * TMAX; i += 256)
                g_cnt[i] = ((i % TMAX) == 0) ? (unsigned)NCTA : 0u;
        } else {
            for (int i = tid; i < 4 * 2 * H; i += 256) g_h[i] = 0.0f;
        }
        return;
    }

    const int d  = bid >> 4;
    const int rb = bid & 15;
    const int T  = (d < 2) ? LPEP : LHLA;
    const float* src = (d < 2) ? in_pep : in_hla;
    const bool rev = (d & 1);

    for (int i = tid; i < T * 21; i += 256) {
        int t = i / 21, j = i - t * 21;
        int ts = rev ? (T - 1 - t) : t;
        sx[t * 21 + j] = src[ts * 21 + j];
    }
    __syncthreads();

    const int row = rb * 256 + tid;
    float w[21];
    const float* wp = p.wih[d] + (size_t)row * 21;
#pragma unroll
    for (int j = 0; j < 21; ++j) w[j] = wp[j];
    const float b = p.bih[d][row] + p.bhh[d][row];

    float* out = g_xg + (size_t)d * LHLA * G4 + row;
    for (int t = 0; t < T; ++t) {
        float acc = b;
#pragma unroll
        for (int j = 0; j < 21; ++j) acc = fmaf(w[j], sx[t * 21 + j], acc);
        out[(size_t)t * G4] = acc;
    }
}

// ---------------------------------------------------------------------------
// Persistent BiLSTM kernel: 512 threads; HMMA GEMV, weights in registers.
// Row map: row r (0..31) = gate (r>>3) * 8 + unit (r&7) of this CTA's slice.
// ---------------------------------------------------------------------------
__global__ void __launch_bounds__(NTHR, 1) lstm_kernel(Ptrs p)
{
    __shared__ __half2 hh[2][512];      // per-group h(t) as half2
    __shared__ float   part[2][4][32];  // per-group per-K-slice row partials

    const int tid  = threadIdx.x;
    const int lane = tid & 31;
    const int warp = tid >> 5;
    const int cta  = blockIdx.x;
    const int grpb = (warp >= 8);       // 0 = dir f, 1 = dir b
    const int w    = warp & 7;
    const int qloc = tid & 255;
    const int g    = lane >> 2;         // mma group id (0..7)
    const int t4   = lane & 3;          // thread-in-group (0..3)
    const int m    = w & 1;             // M fragment: rows [m*16, m*16+16)
    const int ks   = w >> 1;            // K slice: cols [ks*256, ks*256+256)
    const int barid = 1 + grpb;

    for (int phase = 0; phase < 2; ++phase) {
        const int d = 2 * phase + grpb;
        const int T = phase ? LHLA : LPEP;
        const float* whh = p.whh[d];

        // ---- preload A fragments (weights) into registers: 16 x 4 half2 ----
        unsigned areg[64];
        {
            const int row0 = m * 16 + g;          // frag rows g and g+8
            const int row1 = row0 + 8;
            const size_t gr0 = ((size_t)((row0 >> 3) * H + 8 * cta + (row0 & 7))) * H;
            const size_t gr1 = ((size_t)((row1 >> 3) * H + 8 * cta + (row1 & 7))) * H;
#pragma unroll
            for (int c = 0; c < 16; ++c) {
                const int k0 = ks * 256 + c * 16 + t4 * 2;
                float2 v0 = *(const float2*)(whh + gr0 + k0);
                float2 v1 = *(const float2*)(whh + gr1 + k0);
                float2 v2 = *(const float2*)(whh + gr0 + k0 + 8);
                float2 v3 = *(const float2*)(whh + gr1 + k0 + 8);
                areg[c * 4 + 0] = h2u(__floats2half2_rn(v0.x, v0.y));
                areg[c * 4 + 1] = h2u(__floats2half2_rn(v1.x, v1.y));
                areg[c * 4 + 2] = h2u(__floats2half2_rn(v2.x, v2.y));
                areg[c * 4 + 3] = h2u(__floats2half2_rn(v3.x, v3.y));
            }
        }
        float c_u = 0.0f;               // cell state: publisher warp lanes 0-7

        float*    hb = g_h + d * 2 * H;
        unsigned* cn = g_cnt + d * TMAX;
        const float* xg = g_xg + (size_t)d * LHLA * G4;
        __syncthreads();

        for (int t = 0; t < T; ++t) {
            // publisher warp: prefetch xg, then acquire-spin the counter
            float x0 = 0.f, x1 = 0.f, x2 = 0.f, x3 = 0.f;
            if (w == 0) {
                if (lane < 8) {
                    const float* xp = xg + (size_t)t * G4 + 8 * cta + lane;
                    x0 = __ldg(xp);
                    x1 = __ldg(xp + H);
                    x2 = __ldg(xp + 2 * H);
                    x3 = __ldg(xp + 3 * H);
                }
                if (lane == 0) {
                    unsigned spins = 0;
                    while (ld_acquire(&cn[t]) < (unsigned)NCTA &&
                           ++spins < SPIN_LIMIT)
                        ;
                }
            }
            GROUP_BAR(barid);           // h(t) globally ready

            // burst fetch + fp32->half2 convert into SMEM
            const int par = t & 1;
            {
                float4 v = __ldcg((const float4*)(hb + par * H) + qloc);
                hh[grpb][2 * qloc]     = __floats2half2_rn(v.x, v.y);
                hh[grpb][2 * qloc + 1] = __floats2half2_rn(v.z, v.w);
            }
            GROUP_BAR(barid);           // hh ready

            // ---- 16 HMMA: rows [m*16,m*16+16) x K slice [ks*256,+256) ----
            float d0 = 0.f, d1 = 0.f, d2 = 0.f, d3 = 0.f;
            const __half2* hv = hh[grpb] + ks * 128;
#pragma unroll
            for (int c = 0; c < 16; ++c) {
                unsigned b0 = h2u(hv[c * 8 + t4]);      // k = c*16 + t4*2 +{0,1}
                unsigned b1 = h2u(hv[c * 8 + 4 + t4]);  // k = c*16+8+t4*2 +{0,1}
                mma16816(d0, d1, d2, d3,
                         areg[c * 4 + 0], areg[c * 4 + 1],
                         areg[c * 4 + 2], areg[c * 4 + 3], b0, b1);
            }
            // col 0 lives in lanes with t4 == 0: d0 = row m*16+g, d2 = +8
            if (t4 == 0) {
                part[grpb][ks][m * 16 + g]     = d0;
                part[grpb][ks][m * 16 + g + 8] = d2;
            }
            GROUP_BAR(barid);           // partials ready

            // ---- publisher: combine slices, cell, publish ----
            if (w == 0) {
                if (lane < 8) {
                    float zi = part[grpb][0][lane]      + part[grpb][1][lane]
                             + part[grpb][2][lane]      + part[grpb][3][lane]      + x0;
                    float zf = part[grpb][0][8 + lane]  + part[grpb][1][8 + lane]
                             + part[grpb][2][8 + lane]  + part[grpb][3][8 + lane]  + x1;
                    float zg = part[grpb][0][16 + lane] + part[grpb][1][16 + lane]
                             + part[grpb][2][16 + lane] + part[grpb][3][16 + lane] + x2;
                    float zo = part[grpb][0][24 + lane] + part[grpb][1][24 + lane]
                             + part[grpb][2][24 + lane] + part[grpb][3][24 + lane] + x3;
                    c_u = fmaf(sigmoid_fast(zf), c_u,
                               sigmoid_fast(zi) * tanh_fast(zg));
                    float hn = sigmoid_fast(zo) * tanh_fast(c_u);
                    __stcg(&hb[((t + 1) & 1) * H + 8 * cta + lane], hn);
                }
                __threadfence();        // ONE membar per dir-group per step
                if (lane == 0) red_add_gpu(&cn[t + 1], 1u);
            }
        }
        __syncthreads();                // phase weights reload barrier
    }
}

// ---------------------------------------------------------------------------
// MLP: h1 = relu(x @ w1.T + b1), y = h1 @ w2.T + b2.
// x = [pep_f, pep_b, hla_f, hla_b]; pep finals in buf 1 (T=15), hla in buf 0.
// ---------------------------------------------------------------------------
__global__ void mlp1_kernel(const float* __restrict__ w1, const float* __restrict__ b1)
{
    __shared__ float sx[G4];
    const int tid = threadIdx.x, lane = tid & 31, warp = tid >> 5;

    for (int k = tid; k < G4; k += 256) {
        int dd = k >> 10;
        int kk = k & 1023;
        int buf = (dd < 2) ? 1 : 0;    // pep T=15 -> buf 1, hla T=372 -> buf 0
        sx[k] = g_h[dd * 2 * H + buf * H + kk];
    }
    __syncthreads();

#pragma unroll
    for (int rep = 0; rep < 2; ++rep) {
        const int j = blockIdx.x * 16 + rep * 8 + warp;
        const float* wrow = w1 + (size_t)j * G4;
        float acc = 0.0f;
#pragma unroll 8
        for (int i = 0; i < 128; ++i)
            acc = fmaf(wrow[i * 32 + lane], sx[i * 32 + lane], acc);
        acc += __shfl_xor_sync(0xffffffffu, acc, 16);
        acc += __shfl_xor_sync(0xffffffffu, acc, 8);
        acc += __shfl_xor_sync(0xffffffffu, acc, 4);
        acc += __shfl_xor_sync(0xffffffffu, acc, 2);
        acc += __shfl_xor_sync(0xffffffffu, acc, 1);
        if (lane == 0) g_h1[j] = fmaxf(acc + b1[j], 0.0f);
    }
}

__global__ void mlp2_kernel(const float* __restrict__ w2, const float* __restrict__ b2,
                            float* __restrict__ out)
{
    __shared__ float red[32];
    const int tid = threadIdx.x, lane = tid & 31, warp = tid >> 5;
    float acc = 0.0f;
    for (int k = tid; k < G4; k += 1024)
        acc = fmaf(g_h1[k], w2[k], acc);
    acc += __shfl_xor_sync(0xffffffffu, acc, 16);
    acc += __shfl_xor_sync(0xffffffffu, acc, 8);
    acc += __shfl_xor_sync(0xffffffffu, acc, 4);
    acc += __shfl_xor_sync(0xffffffffu, acc, 2);
    acc += __shfl_xor_sync(0xffffffffu, acc, 1);
    if (lane == 0) red[warp] = acc;
    __syncthreads();
    if (warp == 0) {
        float v = red[lane];
        v += __shfl_xor_sync(0xffffffffu, v, 16);
        v += __shfl_xor_sync(0xffffffffu, v, 8);
        v += __shfl_xor_sync(0xffffffffu, v, 4);
        v += __shfl_xor_sync(0xffffffffu, v, 2);
        v += __shfl_xor_sync(0xffffffffu, v, 1);
        if (lane == 0) out[0] = v + b2[0];
    }
}

// ---------------------------------------------------------------------------
extern "C" void kernel_launch(void* const* d_in, const int* in_sizes, int n_in,
                              void* d_out, int out_size)
{
    (void)in_sizes; (void)n_in; (void)out_size;

    const float* in_pep = (const float*)d_in[0];
    const float* in_hla = (const float*)d_in[1];

    Ptrs p;
    // input order: [wih, whh, bih, bhh] for pep_f, pep_b, hla_f, hla_b
    for (int d = 0; d < 4; ++d) {
        p.wih[d] = (const float*)d_in[2 + 4 * d];
        p.whh[d] = (const float*)d_in[3 + 4 * d];
        p.bih[d] = (const float*)d_in[4 + 4 * d];
        p.bhh[d] = (const float*)d_in[5 + 4 * d];
    }
    const float* w1 = (const float*)d_in[18];
    const float* b1 = (const float*)d_in[19];
    const float* w2 = (const float*)d_in[20];
    const float* b2 = (const float*)d_in[21];

    prep_kernel<<<66, 256>>>(in_pep, in_hla, p);
    lstm_kernel<<<NCTA, NTHR>>>(p);
    mlp1_kernel<<<256, 256>>>(w1, b1);
    mlp2_kernel<<<1, 1024>>>(w2, b2, (float*)d_out);
}